// round 13
// baseline (speedup 1.0000x reference)
#include <cuda_runtime.h>
#include <cuda_bf16.h>
#include <math.h>

#define DD 512
#define MM 2048
#define BB 4
#define KK 8
#define NN 8192
#define MB_ (MM*BB)               // 8192 floats per h_all row
#define PTOT (NN/2)               // 4096 row-pairs total
#define EPSV 1e-8f

// Scratch (device globals: allocation-free rule)
// Packed bf16 dictionary: g_Vtp[(2m+bp)*DD + d] = (V[d,m,2bp], V[d,m,2bp+1])
__device__ __nv_bfloat162 g_Vtp[(size_t)MM * 2 * DD];   // 8 MB
__device__ float g_esum[MM];
__device__ float g_counts[MM];
__device__ float g_acc[3];                 // cap, rec, unc (sums over rows)
__device__ unsigned g_done;

// Tiled transpose+pack: V (D, M*B) f32 -> Vtp (M*2, D) bf16x2.
__global__ void transpose_kernel(const float* __restrict__ V) {
    __shared__ float tile[32][33];
    if (blockIdx.x == 0 && blockIdx.y == 0) {
        int t = threadIdx.y * 32 + threadIdx.x;
        #pragma unroll
        for (int j = 0; j < 8; j++) { g_esum[t + 256*j] = 0.0f; g_counts[t + 256*j] = 0.0f; }
        if (t < 3) g_acc[t] = 0.0f;
        if (t == 0) g_done = 0u;
    }
    int mb0 = blockIdx.x * 32;
    int d0  = blockIdx.y * 32;
    int tx = threadIdx.x, ty = threadIdx.y;   // 32 x 8
    #pragma unroll
    for (int i = 0; i < 32; i += 8)
        tile[ty + i][tx] = V[(size_t)(d0 + ty + i) * MB_ + mb0 + tx];
    __syncthreads();
    #pragma unroll
    for (int iter = 0; iter < 2; iter++) {
        int ro = ty + 8 * iter;                // 0..15
        float lo = tile[tx][2 * ro];
        float hi = tile[tx][2 * ro + 1];
        g_Vtp[(size_t)(mb0 / 2 + ro) * DD + d0 + tx] = __floats2bfloat162_rn(lo, hi);
    }
}

// warp argmax over (value-bits desc, index asc): REDUX pair.
__device__ __forceinline__ void warp_argmax(unsigned vbits, int m,
                                            unsigned &win_v, int &win_m) {
    unsigned mx = __reduce_max_sync(0xffffffffu, vbits);
    unsigned cand = (vbits == mx) ? (unsigned)m : 0xffffffffu;
    win_m = (int)__reduce_min_sync(0xffffffffu, cand);
    win_v = mx;
}

// One B1 round: extract current max of both rows' register sets, publish candidates.
__device__ __forceinline__ void b1_round(unsigned ebA[8], unsigned ebB[8],
    int mbase, int lane, int warp, int kk,
    unsigned* cvAb, int* cmAb, unsigned* cvBb, int* cmBb)
{
    unsigned bvA = ebA[0]; int bjA = 0;
    #pragma unroll
    for (int j = 1; j < 8; j++) if (ebA[j] > bvA) { bvA = ebA[j]; bjA = j; }
    int bmA = mbase + 32 * bjA;
    unsigned bvB = ebB[0]; int bjB = 0;
    #pragma unroll
    for (int j = 1; j < 8; j++) if (ebB[j] > bvB) { bvB = ebB[j]; bjB = j; }
    int bmB = mbase + 32 * bjB;

    unsigned wvA; int wmA; warp_argmax(bvA, bmA, wvA, wmA);
    unsigned wvB; int wmB; warp_argmax(bvB, bmB, wvB, wmB);

    #pragma unroll
    for (int j = 0; j < 8; j++) {
        if (wmA == mbase + 32 * j) ebA[j] = 0u;
        if (wmB == mbase + 32 * j) ebB[j] = 0u;
    }
    if (lane == 0) {
        cvAb[warp * 8 + kk] = wvA; cmAb[warp * 8 + kk] = wmA;
        cvBb[warp * 8 + kk] = wvB; cmBb[warp * 8 + kk] = wmB;
    }
}

// One B2 merge round over the 64-candidate lists (register pair, REDUX-only chain).
__device__ __forceinline__ void b2_round(unsigned &c0, unsigned &c1, int &m0, int &m1,
                                         int &selk, float &capadd)
{
    bool p0 = (c0 > c1) || (c0 == c1 && m0 < m1);
    unsigned bv = p0 ? c0 : c1;
    int      bm = p0 ? m0 : m1;
    unsigned wv; int wm; warp_argmax(bv, bm, wv, wm);
    selk = wm;
    capadd = __uint_as_float(wv);
    if (m0 == wm) c0 = 0u;
    if (m1 == wm) c1 = 0u;
}

// One Phase-D gather/FMA step for expert m (4 d's per thread, packed bf16x2).
__device__ __forceinline__ void d_kk(const float4* __restrict__ hrow, int m, int d0,
                                     float &ax, float &ay, float &az, float &aw)
{
    float4 h = hrow[m];                        // uniform address, cache hit
    const __nv_bfloat162* p0 = g_Vtp + (size_t)(2 * m)     * DD + d0;
    const __nv_bfloat162* p1 = g_Vtp + (size_t)(2 * m + 1) * DD + d0;
    uint4 r0 = *(const uint4*)p0;
    uint4 r1 = *(const uint4*)p1;
    const __nv_bfloat162* q0 = (const __nv_bfloat162*)&r0;
    const __nv_bfloat162* q1 = (const __nv_bfloat162*)&r1;
    float2 a0 = __bfloat1622float2(q0[0]), b0 = __bfloat1622float2(q1[0]);
    float2 a1 = __bfloat1622float2(q0[1]), b1 = __bfloat1622float2(q1[1]);
    float2 a2 = __bfloat1622float2(q0[2]), b2 = __bfloat1622float2(q1[2]);
    float2 a3 = __bfloat1622float2(q0[3]), b3 = __bfloat1622float2(q1[3]);
    ax += h.x * a0.x + h.y * a0.y + h.z * b0.x + h.w * b0.y;
    ay += h.x * a1.x + h.y * a1.y + h.z * b1.x + h.w * b1.y;
    az += h.x * a2.x + h.y * a2.y + h.z * b2.x + h.w * b2.y;
    aw += h.x * a3.x + h.y * a3.y + h.z * b3.x + h.w * b3.y;
}

// Phase A for one pair: stream both rows, energies to regs + exclusive smem slots.
__device__ __forceinline__ void phase_a(const float* __restrict__ h_all, int nA,
                                        int mbase, unsigned ebA[8], unsigned ebB[8],
                                        float* s_esum)
{
    const float4* hA = (const float4*)(h_all + (size_t)nA * MB_);
    const float4* hB = (const float4*)(h_all + (size_t)(nA + 1) * MB_);
    #pragma unroll
    for (int j = 0; j < 8; j++) {
        float4 a = __ldcs(&hA[mbase + 32 * j]);
        float4 b = __ldcs(&hB[mbase + 32 * j]);
        float ea = fmaf(a.x, a.x, fmaf(a.y, a.y, fmaf(a.z, a.z, a.w * a.w)));
        float ec = fmaf(b.x, b.x, fmaf(b.y, b.y, fmaf(b.z, b.z, b.w * b.w)));
        s_esum[mbase + 32 * j] += ea + ec;     // exclusive slot, no atomics
        ebA[j] = __float_as_uint(ea);
        ebB[j] = __float_as_uint(ec);
    }
}

__global__ __launch_bounds__(256, 4)
void main_kernel(const float* __restrict__ x_flat,
                 const float* __restrict__ h_all,
                 float* __restrict__ out) {
    __shared__ unsigned cvA[2][64], cvB[2][64];
    __shared__ int      cmA[2][64], cmB[2][64];
    __shared__ float    s_esum[MM];            // exclusive per-thread slots
    __shared__ float    red_a[8], red_b[8];
    __shared__ unsigned s_last;

    const int t = threadIdx.x;
    const int warp = t >> 5, lane = t & 31;
    const int mbase = warp * 256 + lane;
    const int half = warp >> 2;                // 0: row A duty, 1: row B duty
    const int t2 = t & 127;
    const int d0 = 4 * t2;
    const bool merger = (warp & 3) == 0;

    // balanced pair range for this block (grid = 4 * #SM, one wave)
    const int p0 = (int)(((long long)blockIdx.x * PTOT) / gridDim.x);
    const int p1 = (int)(((long long)(blockIdx.x + 1) * PTOT) / gridDim.x);
    const int np = p1 - p0;

    #pragma unroll
    for (int j = 0; j < 8; j++) s_esum[mbase + 32 * j] = 0.0f;

    float unc_acc = 0.0f, rec_acc = 0.0f, cap_acc = 0.0f;

    float* out_hs  = out;                          // (N, K, B)
    float* out_idx = out + (size_t)NN * KK * BB;   // (N, K) as float

    unsigned ebA[8], ebB[8];
    int sel[KK];

    // ---- prologue: A(p0), B1(p0), bar, B2(p0) redundant register merge ----
    phase_a(h_all, 2 * p0, mbase, ebA, ebB, s_esum);
    #pragma unroll
    for (int kk = 0; kk < KK; kk++)
        b1_round(ebA, ebB, mbase, lane, warp, kk, cvA[0], cmA[0], cvB[0], cmB[0]);
    __syncthreads();
    {
        const unsigned* cvb = half ? cvB[0] : cvA[0];
        const int*      cmb = half ? cmB[0] : cmA[0];
        unsigned c0 = cvb[lane], c1 = cvb[lane + 32];
        int      m0 = cmb[lane], m1 = cmb[lane + 32];
        #pragma unroll
        for (int kk = 0; kk < KK; kk++) {
            float capadd;
            b2_round(c0, c1, m0, m1, sel[kk], capadd);
            if (merger && lane == 0) cap_acc += capadd;
        }
    }

    // ---- pipelined main loop over pairs p0 .. p0+np-2 ----
    #pragma unroll 1
    for (int i = 0; i < np - 1; i++) {
        const int bufn = (i + 1) & 1;
        const int pcur = p0 + i;
        const int ncur = 2 * pcur + half;
        const float4* hcur = (const float4*)(h_all + (size_t)ncur * MB_);

        // S1: A(i+1); B1(i+1) interleaved with D(i) kk0..3; C(i)
        phase_a(h_all, 2 * (pcur + 1), mbase, ebA, ebB, s_esum);
        float ax = 0.f, ay = 0.f, az = 0.f, aw = 0.f;
        #pragma unroll
        for (int kk = 0; kk < KK; kk++) {
            b1_round(ebA, ebB, mbase, lane, warp, kk,
                     cvA[bufn], cmA[bufn], cvB[bufn], cmB[bufn]);
            if (kk < 4) d_kk(hcur, sel[kk], d0, ax, ay, az, aw);
        }
        if (merger && lane < KK) {
            int mym = sel[0];
            #pragma unroll
            for (int kk = 1; kk < KK; kk++) if (lane == kk) mym = sel[kk];
            out_idx[(size_t)ncur * KK + lane] = (float)mym;
            float4 h = hcur[mym];
            ((float4*)(out_hs + (size_t)ncur * KK * BB))[lane] = h;
            atomicAdd(&g_counts[mym], 1.0f);
        }
        __syncthreads();

        // S2: B2(i+1) redundant register merge, in place; rounds 0..3 overwrite
        //     sel[0..3] (consumed in S1) while d_kk consumes old sel[4..7].
        {
            const unsigned* cvb = half ? cvB[bufn] : cvA[bufn];
            const int*      cmb = half ? cmB[bufn] : cmA[bufn];
            unsigned c0 = cvb[lane], c1 = cvb[lane + 32];
            int      m0 = cmb[lane], m1 = cmb[lane + 32];
            #pragma unroll
            for (int kk = 0; kk < 4; kk++) {
                float capadd;
                int mold = sel[kk + 4];            // old pair-i selection
                b2_round(c0, c1, m0, m1, sel[kk], capadd);
                if (merger && lane == 0) cap_acc += capadd;
                d_kk(hcur, mold, d0, ax, ay, az, aw);
            }
            float4 xv = __ldcs((const float4*)(x_flat + (size_t)ncur * DD + d0));
            #pragma unroll
            for (int kk = 4; kk < KK; kk++) {
                float capadd;
                b2_round(c0, c1, m0, m1, sel[kk], capadd);
                if (merger && lane == 0) cap_acc += capadd;
            }
            // residual(i)
            float rx = xv.x - ax, ry = xv.y - ay, rz = xv.z - az, rw = xv.w - aw;
            unc_acc += rx * rx + ry * ry + rz * rz + rw * rw;
            rec_acc += ax * ax + ay * ay + az * az + aw * aw;
        }
    }

    // ---- epilogue: last pair ----
    {
        const int ncur = 2 * (p0 + np - 1) + half;
        const float4* hcur = (const float4*)(h_all + (size_t)ncur * MB_);
        float ax = 0.f, ay = 0.f, az = 0.f, aw = 0.f;
        #pragma unroll
        for (int kk = 0; kk < KK; kk++)
            d_kk(hcur, sel[kk], d0, ax, ay, az, aw);
        if (merger && lane < KK) {
            int mym = sel[0];
            #pragma unroll
            for (int kk = 1; kk < KK; kk++) if (lane == kk) mym = sel[kk];
            out_idx[(size_t)ncur * KK + lane] = (float)mym;
            float4 h = hcur[mym];
            ((float4*)(out_hs + (size_t)ncur * KK * BB))[lane] = h;
            atomicAdd(&g_counts[mym], 1.0f);
        }
        float4 xv = __ldcs((const float4*)(x_flat + (size_t)ncur * DD + d0));
        float rx = xv.x - ax, ry = xv.y - ay, rz = xv.z - az, rw = xv.w - aw;
        unc_acc += rx * rx + ry * ry + rz * rz + rw * rw;
        rec_acc += ax * ax + ay * ay + az * az + aw * aw;
    }

    // ---- flush block accumulators (once per kernel) ----
    #pragma unroll
    for (int j = 0; j < 8; j++)
        atomicAdd(&g_esum[mbase + 32 * j], s_esum[mbase + 32 * j]);
    #pragma unroll
    for (int off = 16; off; off >>= 1) {
        unc_acc += __shfl_down_sync(0xffffffffu, unc_acc, off);
        rec_acc += __shfl_down_sync(0xffffffffu, rec_acc, off);
    }
    if (lane == 0) {
        atomicAdd(&g_acc[2], unc_acc);
        atomicAdd(&g_acc[1], rec_acc);
        if (merger) atomicAdd(&g_acc[0], cap_acc);
    }
    __threadfence();
    __syncthreads();
    if (t == 0) s_last = (atomicAdd(&g_done, 1u) == gridDim.x - 1) ? 1u : 0u;
    __syncthreads();
    if (!s_last) return;

    // ---- last-block finalize ----
    {
        float s = 0.0f;
        #pragma unroll
        for (int j = 0; j < 8; j++) s += __ldcg(&g_esum[t + 256 * j]);
        #pragma unroll
        for (int off = 16; off; off >>= 1) s += __shfl_down_sync(0xffffffffu, s, off);
        if (lane == 0) red_a[warp] = s;
        __syncthreads();
        __shared__ float s_denom;
        if (t == 0) {
            float tot = 0.0f;
            #pragma unroll
            for (int w = 0; w < 8; w++) tot += red_a[w];
            s_denom = fmaxf(tot / (float)NN, EPSV);
        }
        __syncthreads();
        const float denom = s_denom;

        float ent = 0.0f, low = 0.0f, dead = 0.0f;
        const float expected = (float)KK / (float)MM * (float)NN;  // 32
        #pragma unroll
        for (int j = 0; j < 8; j++) {
            int m = t + 256 * j;
            float avg = __ldcg(&g_esum[m]) / (float)NN;
            float p = fmaxf(avg / denom, EPSV);
            ent += -p * logf(p);
            float c = __ldcg(&g_counts[m]);
            if (c <= 0.1f * expected)  low  += 1.0f;
            if (c <= 0.01f * expected) dead += 1.0f;
        }
        #pragma unroll
        for (int off = 16; off; off >>= 1) {
            ent  += __shfl_down_sync(0xffffffffu, ent,  off);
            low  += __shfl_down_sync(0xffffffffu, low,  off);
            dead += __shfl_down_sync(0xffffffffu, dead, off);
        }
        if (lane == 0) { red_a[warp] = ent; red_b[warp] = low; cvA[0][warp] = __float_as_uint(dead); }
        __syncthreads();
        if (t == 0) {
            float E = 0.0f, L = 0.0f, Dd = 0.0f;
            #pragma unroll
            for (int w = 0; w < 8; w++) {
                E += red_a[w]; L += red_b[w]; Dd += __uint_as_float(cvA[0][w]);
            }
            float entropy = E / logf((float)MM);
            float cap = __ldcg(&g_acc[0]) / (float)NN;
            float rec = __ldcg(&g_acc[1]) / (float)NN;
            float unc = __ldcg(&g_acc[2]) / (float)NN;
            size_t OFF = (size_t)NN * KK * BB + (size_t)NN * KK;  // 327680
            out[OFF + 0] = cap;
            out[OFF + 1] = rec;
            out[OFF + 2] = unc;
            out[OFF + 3] = entropy;
            out[OFF + 4] = unc + 0.01f * (1.0f - entropy);
            out[OFF + 5] = L;
            out[OFF + 6] = Dd;
        }
    }
}

extern "C" void kernel_launch(void* const* d_in, const int* in_sizes, int n_in,
                              void* d_out, int out_size) {
    const float* x_flat = (const float*)d_in[0];   // (N, D)
    const float* h_all  = (const float*)d_in[1];   // (N, M, B)
    const float* V      = (const float*)d_in[2];   // (D, M, B)
    float* out = (float*)d_out;

    dim3 tb(32, 8);
    dim3 tg(MB_ / 32, DD / 32);    // (256, 16)
    transpose_kernel<<<tg, tb>>>(V);

    int dev = 0, nsm = 148;
    cudaGetDevice(&dev);
    cudaDeviceGetAttribute(&nsm, cudaDevAttrMultiProcessorCount, dev);
    int grid = 4 * nsm;            // one full wave at 4 CTAs/SM
    if (grid > PTOT) grid = PTOT;

    main_kernel<<<grid, 256>>>(x_flat, h_all, out);
}

// round 14
// speedup vs baseline: 1.7577x; 1.7577x over previous
#include <cuda_runtime.h>
#include <cuda_bf16.h>
#include <math.h>

#define DD 512
#define MM 2048
#define BB 4
#define KK 8
#define NN 8192
#define MB_ (MM*BB)               // 8192 floats per h_all row
#define PTOT (NN/2)               // 4096 row-pairs total
#define EPSV 1e-8f

// Scratch (device globals: allocation-free rule)
// Packed bf16 dictionary: g_Vtp[(2m+bp)*DD + d] = (V[d,m,2bp], V[d,m,2bp+1])
__device__ __nv_bfloat162 g_Vtp[(size_t)MM * 2 * DD];   // 8 MB
__device__ float g_esum[MM];
__device__ float g_counts[MM];
__device__ float g_acc[3];                 // cap, rec, unc (sums over rows)
__device__ unsigned g_done;

// Tiled transpose+pack: V (D, M*B) f32 -> Vtp (M*2, D) bf16x2.
__global__ void transpose_kernel(const float* __restrict__ V) {
    __shared__ float tile[32][33];
    if (blockIdx.x == 0 && blockIdx.y == 0) {
        int t = threadIdx.y * 32 + threadIdx.x;
        #pragma unroll
        for (int j = 0; j < 8; j++) { g_esum[t + 256*j] = 0.0f; g_counts[t + 256*j] = 0.0f; }
        if (t < 3) g_acc[t] = 0.0f;
        if (t == 0) g_done = 0u;
    }
    int mb0 = blockIdx.x * 32;
    int d0  = blockIdx.y * 32;
    int tx = threadIdx.x, ty = threadIdx.y;   // 32 x 8
    #pragma unroll
    for (int i = 0; i < 32; i += 8)
        tile[ty + i][tx] = V[(size_t)(d0 + ty + i) * MB_ + mb0 + tx];
    __syncthreads();
    #pragma unroll
    for (int iter = 0; iter < 2; iter++) {
        int ro = ty + 8 * iter;                // 0..15
        float lo = tile[tx][2 * ro];
        float hi = tile[tx][2 * ro + 1];
        g_Vtp[(size_t)(mb0 / 2 + ro) * DD + d0 + tx] = __floats2bfloat162_rn(lo, hi);
    }
}

// warp argmax over (value-bits desc, index asc): REDUX pair.
__device__ __forceinline__ void warp_argmax(unsigned vbits, int m,
                                            unsigned &win_v, int &win_m) {
    unsigned mx = __reduce_max_sync(0xffffffffu, vbits);
    unsigned cand = (vbits == mx) ? (unsigned)m : 0xffffffffu;
    win_m = (int)__reduce_min_sync(0xffffffffu, cand);
    win_v = mx;
}

// One B1 round: extract current max of both rows' register sets, publish candidates.
__device__ __forceinline__ void b1_round(unsigned ebA[8], unsigned ebB[8],
    int mbase, int lane, int warp, int kk,
    unsigned* cvAb, int* cmAb, unsigned* cvBb, int* cmBb)
{
    unsigned bvA = ebA[0]; int bjA = 0;
    #pragma unroll
    for (int j = 1; j < 8; j++) if (ebA[j] > bvA) { bvA = ebA[j]; bjA = j; }
    int bmA = mbase + 32 * bjA;
    unsigned bvB = ebB[0]; int bjB = 0;
    #pragma unroll
    for (int j = 1; j < 8; j++) if (ebB[j] > bvB) { bvB = ebB[j]; bjB = j; }
    int bmB = mbase + 32 * bjB;

    unsigned wvA; int wmA; warp_argmax(bvA, bmA, wvA, wmA);
    unsigned wvB; int wmB; warp_argmax(bvB, bmB, wvB, wmB);

    #pragma unroll
    for (int j = 0; j < 8; j++) {
        if (wmA == mbase + 32 * j) ebA[j] = 0u;
        if (wmB == mbase + 32 * j) ebB[j] = 0u;
    }
    if (lane == 0) {
        cvAb[warp * 8 + kk] = wvA; cmAb[warp * 8 + kk] = wmA;
        cvBb[warp * 8 + kk] = wvB; cmBb[warp * 8 + kk] = wmB;
    }
}

// One Phase-D gather/FMA step for expert m (4 d's per thread, packed bf16x2).
__device__ __forceinline__ void d_kk(const float4* __restrict__ hrow, int m, int d0,
                                     float &ax, float &ay, float &az, float &aw)
{
    float4 h = hrow[m];                        // uniform address, cache hit
    const __nv_bfloat162* p0 = g_Vtp + (size_t)(2 * m)     * DD + d0;
    const __nv_bfloat162* p1 = g_Vtp + (size_t)(2 * m + 1) * DD + d0;
    uint4 r0 = *(const uint4*)p0;
    uint4 r1 = *(const uint4*)p1;
    const __nv_bfloat162* q0 = (const __nv_bfloat162*)&r0;
    const __nv_bfloat162* q1 = (const __nv_bfloat162*)&r1;
    float2 a0 = __bfloat1622float2(q0[0]), b0 = __bfloat1622float2(q1[0]);
    float2 a1 = __bfloat1622float2(q0[1]), b1 = __bfloat1622float2(q1[1]);
    float2 a2 = __bfloat1622float2(q0[2]), b2 = __bfloat1622float2(q1[2]);
    float2 a3 = __bfloat1622float2(q0[3]), b3 = __bfloat1622float2(q1[3]);
    ax += h.x * a0.x + h.y * a0.y + h.z * b0.x + h.w * b0.y;
    ay += h.x * a1.x + h.y * a1.y + h.z * b1.x + h.w * b1.y;
    az += h.x * a2.x + h.y * a2.y + h.z * b2.x + h.w * b2.y;
    aw += h.x * a3.x + h.y * a3.y + h.z * b3.x + h.w * b3.y;
}

// Phase A for one pair: stream both rows, energies to regs + exclusive smem slots.
__device__ __forceinline__ void phase_a(const float* __restrict__ h_all, int nA,
                                        int mbase, unsigned ebA[8], unsigned ebB[8],
                                        float* s_esum)
{
    const float4* hA = (const float4*)(h_all + (size_t)nA * MB_);
    const float4* hB = (const float4*)(h_all + (size_t)(nA + 1) * MB_);
    #pragma unroll
    for (int j = 0; j < 8; j++) {
        float4 a = __ldcs(&hA[mbase + 32 * j]);
        float4 b = __ldcs(&hB[mbase + 32 * j]);
        float ea = fmaf(a.x, a.x, fmaf(a.y, a.y, fmaf(a.z, a.z, a.w * a.w)));
        float ec = fmaf(b.x, b.x, fmaf(b.y, b.y, fmaf(b.z, b.z, b.w * b.w)));
        s_esum[mbase + 32 * j] += ea + ec;     // exclusive slot, no atomics
        ebA[j] = __float_as_uint(ea);
        ebB[j] = __float_as_uint(ec);
    }
}

__global__ __launch_bounds__(256, 4)
void main_kernel(const float* __restrict__ x_flat,
                 const float* __restrict__ h_all,
                 float* __restrict__ out) {
    __shared__ unsigned cvA[2][64], cvB[2][64];
    __shared__ int      cmA[2][64], cmB[2][64];
    __shared__ float    s_esum[MM];            // exclusive per-thread slots
    __shared__ float    red_a[8], red_b[8];
    __shared__ unsigned s_last;

    const int t = threadIdx.x;
    const int warp = t >> 5, lane = t & 31;
    const int mbase = warp * 256 + lane;
    const int half = warp >> 2;                // 0: row A duty, 1: row B duty
    const int t2 = t & 127;
    const int d0 = 4 * t2;
    const bool merger = (warp & 3) == 0;

    // balanced pair range for this block (grid = 4 * #SM, one wave)
    const int p0 = (int)(((long long)blockIdx.x * PTOT) / gridDim.x);
    const int p1 = (int)(((long long)(blockIdx.x + 1) * PTOT) / gridDim.x);
    const int np = p1 - p0;

    #pragma unroll
    for (int j = 0; j < 8; j++) s_esum[mbase + 32 * j] = 0.0f;

    float unc_acc = 0.0f, rec_acc = 0.0f, cap_acc = 0.0f;

    float* out_hs  = out;                          // (N, K, B)
    float* out_idx = out + (size_t)NN * KK * BB;   // (N, K) as float

    unsigned ebA[8], ebB[8];
    int sel[KK];

    // ---- prologue: A(p0), B1(p0), bar, merge-B2(p0) ----
    phase_a(h_all, 2 * p0, mbase, ebA, ebB, s_esum);
    #pragma unroll
    for (int kk = 0; kk < KK; kk++)
        b1_round(ebA, ebB, mbase, lane, warp, kk, cvA[0], cmA[0], cvB[0], cmB[0]);
    __syncthreads();
    {
        const unsigned* cvb = half ? cvB[0] : cvA[0];
        const int*      cmb = half ? cmB[0] : cmA[0];
        unsigned h0v = 0u, h1v = 0u;
        int      h0m = 0x7fffffff, h1m = 0x7fffffff;
        int pos = 1;
        if (lane < 8) {
            h0v = cvb[lane * 8];     h0m = cmb[lane * 8];
            h1v = cvb[lane * 8 + 1]; h1m = cmb[lane * 8 + 1];
        }
        #pragma unroll
        for (int kk = 0; kk < KK; kk++) {
            unsigned wv; int wm;
            warp_argmax(h0v, h0m, wv, wm);
            sel[kk] = wm;
            if (merger && lane == 0) cap_acc += __uint_as_float(wv);
            if (lane == (wm >> 8)) {
                h0v = h1v; h0m = h1m;             // promote (on-chain, 4 cyc)
                pos++;
                h1v = cvb[lane * 8 + pos];        // prefetch (off-chain)
                h1m = cmb[lane * 8 + pos];
            }
        }
    }

    // ---- pipelined main loop over pairs p0 .. p0+np-2 ----
    #pragma unroll 1
    for (int i = 0; i < np - 1; i++) {
        const int bufn = (i + 1) & 1;
        const int pcur = p0 + i;
        const int ncur = 2 * pcur + half;
        const float4* hcur = (const float4*)(h_all + (size_t)ncur * MB_);

        // S1: A(i+1); B1(i+1) interleaved with D(i) kk0..3; C(i)
        phase_a(h_all, 2 * (pcur + 1), mbase, ebA, ebB, s_esum);
        float ax = 0.f, ay = 0.f, az = 0.f, aw = 0.f;
        #pragma unroll
        for (int kk = 0; kk < KK; kk++) {
            b1_round(ebA, ebB, mbase, lane, warp, kk,
                     cvA[bufn], cmA[bufn], cvB[bufn], cmB[bufn]);
            if (kk < 4) d_kk(hcur, sel[kk], d0, ax, ay, az, aw);
        }
        if (merger && lane < KK) {
            int mym = sel[0];
            #pragma unroll
            for (int kk = 1; kk < KK; kk++) if (lane == kk) mym = sel[kk];
            out_idx[(size_t)ncur * KK + lane] = (float)mym;
            float4 h = hcur[mym];
            ((float4*)(out_hs + (size_t)ncur * KK * BB))[lane] = h;
            atomicAdd(&g_counts[mym], 1.0f);
        }
        __syncthreads();

        // S2: merge-B2(i+1), prefetched heads, in place; interleaved with D(i) kk4..7
        {
            const unsigned* cvb = half ? cvB[bufn] : cvA[bufn];
            const int*      cmb = half ? cmB[bufn] : cmA[bufn];
            unsigned h0v = 0u, h1v = 0u;
            int      h0m = 0x7fffffff, h1m = 0x7fffffff;
            int pos = 1;
            if (lane < 8) {
                h0v = cvb[lane * 8];     h0m = cmb[lane * 8];
                h1v = cvb[lane * 8 + 1]; h1m = cmb[lane * 8 + 1];
            }
            #pragma unroll
            for (int kk = 0; kk < 4; kk++) {
                int mold = sel[kk + 4];            // old pair-i selection
                unsigned wv; int wm;
                warp_argmax(h0v, h0m, wv, wm);
                sel[kk] = wm;
                if (merger && lane == 0) cap_acc += __uint_as_float(wv);
                if (lane == (wm >> 8)) {
                    h0v = h1v; h0m = h1m;
                    pos++;
                    h1v = cvb[lane * 8 + pos];
                    h1m = cmb[lane * 8 + pos];
                }
                d_kk(hcur, mold, d0, ax, ay, az, aw);
            }
            float4 xv = __ldcs((const float4*)(x_flat + (size_t)ncur * DD + d0));
            #pragma unroll
            for (int kk = 4; kk < KK; kk++) {
                unsigned wv; int wm;
                warp_argmax(h0v, h0m, wv, wm);
                sel[kk] = wm;
                if (merger && lane == 0) cap_acc += __uint_as_float(wv);
                if (lane == (wm >> 8)) {
                    h0v = h1v; h0m = h1m;
                    pos++;
                    h1v = cvb[lane * 8 + pos];
                    h1m = cmb[lane * 8 + pos];
                }
            }
            float rx = xv.x - ax, ry = xv.y - ay, rz = xv.z - az, rw = xv.w - aw;
            unc_acc += rx * rx + ry * ry + rz * rz + rw * rw;
            rec_acc += ax * ax + ay * ay + az * az + aw * aw;
        }
    }

    // ---- epilogue: last pair ----
    {
        const int ncur = 2 * (p0 + np - 1) + half;
        const float4* hcur = (const float4*)(h_all + (size_t)ncur * MB_);
        float ax = 0.f, ay = 0.f, az = 0.f, aw = 0.f;
        #pragma unroll
        for (int kk = 0; kk < KK; kk++)
            d_kk(hcur, sel[kk], d0, ax, ay, az, aw);
        if (merger && lane < KK) {
            int mym = sel[0];
            #pragma unroll
            for (int kk = 1; kk < KK; kk++) if (lane == kk) mym = sel[kk];
            out_idx[(size_t)ncur * KK + lane] = (float)mym;
            float4 h = hcur[mym];
            ((float4*)(out_hs + (size_t)ncur * KK * BB))[lane] = h;
            atomicAdd(&g_counts[mym], 1.0f);
        }
        float4 xv = __ldcs((const float4*)(x_flat + (size_t)ncur * DD + d0));
        float rx = xv.x - ax, ry = xv.y - ay, rz = xv.z - az, rw = xv.w - aw;
        unc_acc += rx * rx + ry * ry + rz * rz + rw * rw;
        rec_acc += ax * ax + ay * ay + az * az + aw * aw;
    }

    // ---- flush block accumulators (once per kernel) ----
    #pragma unroll
    for (int j = 0; j < 8; j++)
        atomicAdd(&g_esum[mbase + 32 * j], s_esum[mbase + 32 * j]);
    #pragma unroll
    for (int off = 16; off; off >>= 1) {
        unc_acc += __shfl_down_sync(0xffffffffu, unc_acc, off);
        rec_acc += __shfl_down_sync(0xffffffffu, rec_acc, off);
    }
    if (lane == 0) {
        atomicAdd(&g_acc[2], unc_acc);
        atomicAdd(&g_acc[1], rec_acc);
        if (merger) atomicAdd(&g_acc[0], cap_acc);
    }
    __threadfence();
    __syncthreads();
    if (t == 0) s_last = (atomicAdd(&g_done, 1u) == gridDim.x - 1) ? 1u : 0u;
    __syncthreads();
    if (!s_last) return;

    // ---- last-block finalize ----
    {
        float s = 0.0f;
        #pragma unroll
        for (int j = 0; j < 8; j++) s += __ldcg(&g_esum[t + 256 * j]);
        #pragma unroll
        for (int off = 16; off; off >>= 1) s += __shfl_down_sync(0xffffffffu, s, off);
        if (lane == 0) red_a[warp] = s;
        __syncthreads();
        __shared__ float s_denom;
        if (t == 0) {
            float tot = 0.0f;
            #pragma unroll
            for (int w = 0; w < 8; w++) tot += red_a[w];
            s_denom = fmaxf(tot / (float)NN, EPSV);
        }
        __syncthreads();
        const float denom = s_denom;

        float ent = 0.0f, low = 0.0f, dead = 0.0f;
        const float expected = (float)KK / (float)MM * (float)NN;  // 32
        #pragma unroll
        for (int j = 0; j < 8; j++) {
            int m = t + 256 * j;
            float avg = __ldcg(&g_esum[m]) / (float)NN;
            float p = fmaxf(avg / denom, EPSV);
            ent += -p * logf(p);
            float c = __ldcg(&g_counts[m]);
            if (c <= 0.1f * expected)  low  += 1.0f;
            if (c <= 0.01f * expected) dead += 1.0f;
        }
        #pragma unroll
        for (int off = 16; off; off >>= 1) {
            ent  += __shfl_down_sync(0xffffffffu, ent,  off);
            low  += __shfl_down_sync(0xffffffffu, low,  off);
            dead += __shfl_down_sync(0xffffffffu, dead, off);
        }
        if (lane == 0) { red_a[warp] = ent; red_b[warp] = low; cvA[0][warp] = __float_as_uint(dead); }
        __syncthreads();
        if (t == 0) {
            float E = 0.0f, L = 0.0f, Dd = 0.0f;
            #pragma unroll
            for (int w = 0; w < 8; w++) {
                E += red_a[w]; L += red_b[w]; Dd += __uint_as_float(cvA[0][w]);
            }
            float entropy = E / logf((float)MM);
            float cap = __ldcg(&g_acc[0]) / (float)NN;
            float rec = __ldcg(&g_acc[1]) / (float)NN;
            float unc = __ldcg(&g_acc[2]) / (float)NN;
            size_t OFF = (size_t)NN * KK * BB + (size_t)NN * KK;  // 327680
            out[OFF + 0] = cap;
            out[OFF + 1] = rec;
            out[OFF + 2] = unc;
            out[OFF + 3] = entropy;
            out[OFF + 4] = unc + 0.01f * (1.0f - entropy);
            out[OFF + 5] = L;
            out[OFF + 6] = Dd;
        }
    }
}

extern "C" void kernel_launch(void* const* d_in, const int* in_sizes, int n_in,
                              void* d_out, int out_size) {
    const float* x_flat = (const float*)d_in[0];   // (N, D)
    const float* h_all  = (const float*)d_in[1];   // (N, M, B)
    const float* V      = (const float*)d_in[2];   // (D, M, B)
    float* out = (float*)d_out;

    dim3 tb(32, 8);
    dim3 tg(MB_ / 32, DD / 32);    // (256, 16)
    transpose_kernel<<<tg, tb>>>(V);

    int dev = 0, nsm = 148;
    cudaGetDevice(&dev);
    cudaDeviceGetAttribute(&nsm, cudaDevAttrMultiProcessorCount, dev);
    int grid = 4 * nsm;            // one full wave at 4 CTAs/SM
    if (grid > PTOT) grid = PTOT;

    main_kernel<<<grid, 256>>>(x_flat, h_all, out);
}